// round 2
// baseline (speedup 1.0000x reference)
#include <cuda_runtime.h>

// TemporalDecay: out = h + (1-m)*g*(h_fwd - h),
//   g = exp(-relu(delta*W + b)),  delta integer in [1,4],
//   h_fwd[b,t,j] = h_a[b, t-(delta-1), j]   (<= 3 rows back).
//
// Strategy: each thread owns one float4 of channels (col4) for one batch b and
// walks a 16-row time segment serially, keeping the last 4 rows of its channels
// in a rolling register window. The "gather" becomes a register select by delta;
// gamma (only 4 deltas x 4 channels = 16 values per thread) is computed once
// into registers. Memory traffic is exactly: h_a read once, deltas/M read once,
// out written once => 160 MB HBM floor.

static constexpr int Bq = 32, Tq = 2048;
static constexpr int C4 = 64;          // float4s per 256-channel row
static constexpr int SEG = 16;         // t rows per thread
static constexpr int NSEG = Tq / SEG;  // 128
static constexpr int THREADS = 256;
static constexpr int BLOCKS = Bq * C4 * NSEG / THREADS;  // 1024

__global__ void __launch_bounds__(THREADS) decay_kernel(
    const float4* __restrict__ H,      // h_a as float4 [B*T*64]
    const float4* __restrict__ DL,     // deltas as float4 [B*T*16]
    const float4* __restrict__ MM,     // mask as float4 [B*T*16]
    const float4* __restrict__ W4,     // W as float4 [64]
    const float4* __restrict__ B4,     // b as float4 [64]
    float4* __restrict__ OUT)
{
    const int g    = blockIdx.x * THREADS + threadIdx.x;
    const int col4 = g & 63;
    const int seg  = (g >> 6) & (NSEG - 1);
    const int bb   = g >> 13;
    const int t0   = seg * SEG;

    const int hbase = (bb * Tq + t0) * C4 + col4;          // float4 index into H/OUT
    const int dbase = (bb * Tq + t0) * 16 + (col4 & 15);   // float4 index into DL/MM

    // gamma[d][component] for d = 1..4, computed once per thread
    const float4 wv = __ldg(W4 + col4);
    const float4 bv = __ldg(B4 + col4);
    float4 gam[4];
#pragma unroll
    for (int d = 0; d < 4; d++) {
        const float df = (float)(d + 1);
        gam[d].x = __expf(-fmaxf(fmaf(df, wv.x, bv.x), 0.0f));
        gam[d].y = __expf(-fmaxf(fmaf(df, wv.y, bv.y), 0.0f));
        gam[d].z = __expf(-fmaxf(fmaf(df, wv.z, bv.z), 0.0f));
        gam[d].w = __expf(-fmaxf(fmaf(df, wv.w, bv.w), 0.0f));
    }

    // Rolling window: slot (s & 3) holds row t0+s. Halo rows t0-1..t0-3 go in
    // slots 3,2,1. For t0==0 the clamped loads are never selected because the
    // reference clamps delta <= t+1.
    float4 win[4];
    {
        const int tm1 = max(t0 - 1, 0), tm2 = max(t0 - 2, 0), tm3 = max(t0 - 3, 0);
        const int rb = bb * Tq * C4 + col4;
        win[3] = __ldg(H + rb + tm1 * C4);
        win[2] = __ldg(H + rb + tm2 * C4);
        win[1] = __ldg(H + rb + tm3 * C4);
        win[0] = win[3];
    }

#pragma unroll 1
    for (int so = 0; so < SEG / 4; so++) {
#pragma unroll
        for (int s2 = 0; s2 < 4; s2++) {
            const int s = so * 4 + s2;
            const float4 ha = __ldg(H + hbase + s * C4);
            const float4 dl = __ldg(DL + dbase + s * 16);
            const float4 mm = __ldg(MM + dbase + s * 16);

            const float4& w1 = win[(s2 + 3) & 3];  // row t-1
            const float4& w2 = win[(s2 + 2) & 3];  // row t-2
            const float4& w3 = win[(s2 + 1) & 3];  // row t-3

            float4 o;
#define PROC(c)                                                              \
            {                                                                \
                const int d = (int)dl.c;                                     \
                const float f  = (d == 1) ? ha.c                             \
                               : (d == 2) ? w1.c                             \
                               : (d == 3) ? w2.c : w3.c;                     \
                const float gv = (d == 2) ? gam[1].c                         \
                               : (d == 3) ? gam[2].c : gam[3].c;             \
                /* d==1 => f-ha == 0, gv value irrelevant */                 \
                o.c = fmaf((1.0f - mm.c) * gv, f - ha.c, ha.c);              \
            }
            PROC(x) PROC(y) PROC(z) PROC(w)
#undef PROC

            OUT[hbase + s * C4] = o;
            win[s2 & 3] = ha;
        }
    }
}

extern "C" void kernel_launch(void* const* d_in, const int* in_sizes, int n_in,
                              void* d_out, int out_size) {
    const float4* h_a    = (const float4*)d_in[0];
    const float4* deltas = (const float4*)d_in[1];
    const float4* Mmask  = (const float4*)d_in[2];
    const float4* W      = (const float4*)d_in[3];
    const float4* b      = (const float4*)d_in[4];
    float4* out = (float4*)d_out;

    decay_kernel<<<BLOCKS, THREADS>>>(h_a, deltas, Mmask, W, b, out);
}

// round 3
// speedup vs baseline: 1.1464x; 1.1464x over previous
#include <cuda_runtime.h>

// TemporalDecay: out = h + (1-m)*g*(h_fwd - h),
//   g = exp(-relu(delta*W + b)),  delta integer in [1,4],
//   h_fwd[b,t,j] = h_a[b, t-(delta-1), j]   (<= 3 rows back).
//
// R3 design:
//  - gamma table (4 deltas x 256 channels = 4KB) precomputed once by a tiny
//    kernel -> zero MUFU in the hot kernel (R2's hidden 31us MUFU wall).
//  - gather done via a 7-row register window per thread (R2's L1 win), but
//    FULLY UNROLLED: all 19 LDG.128 are independent and issued up front.
//  - no shared memory, no syncthreads, no LDS bank conflicts.

static constexpr int Bq = 32, Tq = 2048;
static constexpr int C4 = 64;          // float4s per 256-channel row
static constexpr int SEG = 4;          // t rows per thread
static constexpr int NSEG = Tq / SEG;  // 512
static constexpr int THREADS = 256;
static constexpr int BLOCKS = Bq * C4 * NSEG / THREADS;  // 4096

// gamma[d-1][channel], laid out as 4 rows of 64 float4s.
__device__ float4 g_gamma4[4 * C4];

__global__ void gamma_precompute_kernel(const float* __restrict__ W,
                                        const float* __restrict__ bias) {
    int j = threadIdx.x;  // 0..255 channel
    float w = W[j];
    float bb = bias[j];
    float* gf = (float*)g_gamma4;
#pragma unroll
    for (int dm = 0; dm < 4; dm++) {
        float x = fmaxf(fmaf((float)(dm + 1), w, bb), 0.0f);
        gf[dm * 256 + j] = __expf(-x);
    }
}

__global__ void __launch_bounds__(THREADS) decay_kernel(
    const float4* __restrict__ H,      // h_a  [B*T*64] float4
    const float4* __restrict__ DL,     // deltas [B*T*16] float4
    const float4* __restrict__ MM,     // mask   [B*T*16] float4
    float4* __restrict__ OUT)
{
    const int g    = blockIdx.x * THREADS + threadIdx.x;
    const int col4 = g & 63;
    const int seg  = (g >> 6) & (NSEG - 1);
    const int bb   = g >> 15;
    const int t0   = seg * SEG;

    const int rb    = bb * Tq * C4 + col4;              // row base into H/OUT
    const int dbase = (bb * Tq + t0) * 16 + (col4 & 15);

    // --- issue all loads up front, fully independent ---
    // R[k] holds row t0-3+k (k=0..2 halo, clamped; k=3..6 the 4 output rows).
    float4 R[7];
#pragma unroll
    for (int k = 0; k < 3; k++) {
        const int t = max(t0 - 3 + k, 0);   // clamped halo never selected at t0==0
        R[k] = __ldg(H + rb + t * C4);
    }
#pragma unroll
    for (int s = 0; s < SEG; s++)
        R[3 + s] = __ldg(H + rb + (t0 + s) * C4);

    float4 dl[SEG], mm[SEG];
#pragma unroll
    for (int s = 0; s < SEG; s++) {
        dl[s] = __ldg(DL + dbase + s * 16);
        mm[s] = __ldg(MM + dbase + s * 16);
    }

    // gamma for this thread's 4 channels, one float4 per delta (L1-hot 4KB).
    float4 gam[4];
#pragma unroll
    for (int d = 0; d < 4; d++)
        gam[d] = __ldg(g_gamma4 + d * C4 + col4);

    // --- compute + store ---
#pragma unroll
    for (int s = 0; s < SEG; s++) {
        const float4 ha = R[3 + s];
        const float4 w1 = R[2 + s];
        const float4 w2 = R[1 + s];
        const float4 w3 = R[0 + s];
        float4 o;
#define PROC(c)                                                          \
        {                                                                \
            const int d = (int)dl[s].c;                                  \
            const float f  = (d == 1) ? ha.c                             \
                           : (d == 2) ? w1.c                             \
                           : (d == 3) ? w2.c : w3.c;                     \
            const float gv = (d == 2) ? gam[1].c                         \
                           : (d == 3) ? gam[2].c : gam[3].c;             \
            /* d==1 => f-ha==0, gv irrelevant */                         \
            o.c = fmaf((1.0f - mm[s].c) * gv, f - ha.c, ha.c);           \
        }
        PROC(x) PROC(y) PROC(z) PROC(w)
#undef PROC
        OUT[rb + (t0 + s) * C4] = o;
    }
}

extern "C" void kernel_launch(void* const* d_in, const int* in_sizes, int n_in,
                              void* d_out, int out_size) {
    const float4* h_a    = (const float4*)d_in[0];
    const float4* deltas = (const float4*)d_in[1];
    const float4* Mmask  = (const float4*)d_in[2];
    const float*  W      = (const float*)d_in[3];
    const float*  b      = (const float*)d_in[4];
    float4* out = (float4*)d_out;

    gamma_precompute_kernel<<<1, 256>>>(W, b);
    decay_kernel<<<BLOCKS, THREADS>>>(h_a, deltas, Mmask, out);
}